// round 16
// baseline (speedup 1.0000x reference)
#include <cuda_runtime.h>
#include <cuda_fp16.h>
#include <mma.h>
#include <cstdint>

using namespace nvcuda;

#define BN     50000
#define NBR    4
#define DD     32
#define CC     128          // NBR*DD
#define MM     256
#define NODES  (BN + MM)    // 50256
#define CAPB   64           // per-type bucket capacity (mean ~20)
#define CSTR   8            // counter stride (ints) -> 32B, no LTS false sharing
#define YROWS  64           // rows per y block

// scratch (static device globals — no allocation)
__device__ __half g_x16[(size_t)NODES * CC];   // 12.9MB X_in fp16 (gather src)
__device__ __half g_xagg16[(size_t)BN * CC];   // aggregation result (y input)
__device__ __half g_wp16[CC * CC];             // W' = blockdiag(W_conv)@W_fc, fp16
__device__ float  g_bp[CC];                    // b'  = b_conv@W_fc + b_fc
__device__ int    g_cntA[BN * CSTR];           // bb counters (32B apart)
__device__ int    g_cntB[BN * CSTR];           // bm counters (32B apart)
__device__ int2   g_entA[(size_t)BN * CAPB];   // bb: (x_byte_off, w_bits)
__device__ int2   g_entB[(size_t)BN * CAPB];   // bm: (vq_byte_off = m*512, w_bits)
__device__ float  g_vq32r[MM * CC];            // vq_grad re-laid [m][b*32+e]
__device__ float  g_vqp[MM * CC];              // vq' = vq @ Wblk^T (128KB, L1-hot)
__device__ float  g_vsum[(size_t)BN * CC];     // per-row sum w*vq' (fp32)
__device__ float  g_info;

// ---------------------------------------------------------------------------
// prep_x: x16 rows + zero counters + relayout vq_grad.
// ---------------------------------------------------------------------------
__global__ void prep_x_kernel(const float* __restrict__ X,
                              const float* __restrict__ codebook,
                              const float* __restrict__ vq_grad,
                              const float* __restrict__ wr_p) {
    const int idx = blockIdx.x * blockDim.x + threadIdx.x;   // NODES*64 half2 units
    if (idx < NODES * 64) {
        const int row = idx >> 6;
        const int c2  = idx & 63;           // half2 column (0..63)
        float2 v;
        if (row < BN) {
            v = ((const float2*)X)[(size_t)row * 64 + c2];
        } else {
            const float wr = wr_p[0];
            const int b = c2 >> 4, sub = c2 & 15, m = row - BN;
            v = ((const float2*)codebook)[((size_t)b * MM + m) * 16 + sub];
            v.x *= wr; v.y *= wr;
        }
        ((__half2*)g_x16)[idx] = __floats2half2_rn(v.x, v.y);
    }
    if (idx < NBR * MM * DD) {
        const int b = idx >> 13;
        const int m = (idx >> 5) & (MM - 1);
        const int e = idx & 31;
        g_vq32r[m * CC + b * DD + e] = vq_grad[idx];
    }
    if (idx < BN) { g_cntA[idx * CSTR] = 0; g_cntB[idx * CSTR] = 0; }
    if (idx == 0) g_info = 0.0f;
}

// ---------------------------------------------------------------------------
// prep_w: block 0..127 -> W'[k][*]; block 128 -> b'; block 129.. -> vq'[m][*]
// ---------------------------------------------------------------------------
__global__ void prep_w_kernel(const float* __restrict__ W_conv,
                              const float* __restrict__ W_fc,
                              const float* __restrict__ b_conv,
                              const float* __restrict__ b_fc) {
    const int t = threadIdx.x;              // 0..127
    const int blk = blockIdx.x;
    if (blk < CC) {
        const int b = blk >> 5, d = blk & 31;
        const float* wrow = W_conv + (b * DD + d) * DD;   // [e]
        float s = 0.0f;
        #pragma unroll
        for (int e = 0; e < DD; e++)
            s = fmaf(wrow[e], W_fc[(b * DD + e) * CC + t], s);
        g_wp16[blk * CC + t] = __float2half_rn(s);
    } else if (blk == CC) {
        float s = b_fc[t];
        for (int k = 0; k < CC; k++)
            s = fmaf(b_conv[k], W_fc[k * CC + t], s);
        g_bp[t] = s;
    } else {
        const int m = blk - CC - 1;
        const int b = t >> 5, d = t & 31;
        const float* wrow = W_conv + (b * DD + d) * DD;   // [e]
        const float* vrow = g_vq32r + m * CC + b * DD;    // [e]
        float s = 0.0f;
        #pragma unroll
        for (int e = 0; e < DD; e++)
            s = fmaf(wrow[e], vrow[e], s);
        g_vqp[m * CC + t] = s;
    }
}

// ---------------------------------------------------------------------------
// fill: dual buckets. bb edges -> entA (x byte off = src*256);
//       bm edges -> entB (vq byte off = c_indices[src]*512).
// ---------------------------------------------------------------------------
__global__ void fill_dst_kernel(const int* __restrict__ sbb, const int* __restrict__ dbb,
                                const float* __restrict__ wbb,
                                const int* __restrict__ sbm, const int* __restrict__ dbm,
                                const float* __restrict__ wbm,
                                const int* __restrict__ cidx, int Ebb, int Etot) {
    const int i = blockIdx.x * blockDim.x + threadIdx.x;
    if (i >= Etot) return;
    if (i < Ebb) {
        const int r = dbb[i];
        const int off = sbb[i] << 8;            // *256 bytes (fp16 row)
        const float w = wbb[i];
        const int pos = atomicAdd(&g_cntA[r * CSTR], 1);
        if (pos < CAPB)
            g_entA[(size_t)r * CAPB + pos] = make_int2(off, __float_as_int(w));
    } else {
        const int j = i - Ebb;
        const int r = dbm[j];
        const int off = cidx[sbm[j]] << 9;      // m*512 bytes (fp32 vq' row)
        const float w = wbm[j];
        const int pos = atomicAdd(&g_cntB[r * CSTR], 1);
        if (pos < CAPB)
            g_entB[(size_t)r * CAPB + pos] = make_int2(off, __float_as_int(w));
    }
}

// ---------------------------------------------------------------------------
// gather v3 (4th launch -> profiled): 16-lane halves, 2 edges per warp-step.
// Lane covers columns sub*8 .. sub*8+7 (16B of fp16 row / 32B of fp32 vq row).
// accL = cols sub*8..+3, accH = cols sub*8+4..+7. Halves merged via shfl_xor 16.
// ---------------------------------------------------------------------------
__device__ __forceinline__ void cvt8_fma(float4& aL, float4& aH, float w, uint4 hv) {
    const float2 f0 = __half22float2(*(const __half2*)&hv.x);
    const float2 f1 = __half22float2(*(const __half2*)&hv.y);
    const float2 f2 = __half22float2(*(const __half2*)&hv.z);
    const float2 f3 = __half22float2(*(const __half2*)&hv.w);
    aL.x = fmaf(w, f0.x, aL.x); aL.y = fmaf(w, f0.y, aL.y);
    aL.z = fmaf(w, f1.x, aL.z); aL.w = fmaf(w, f1.y, aL.w);
    aH.x = fmaf(w, f2.x, aH.x); aH.y = fmaf(w, f2.y, aH.y);
    aH.z = fmaf(w, f3.x, aH.z); aH.w = fmaf(w, f3.y, aH.w);
}

__global__ void gather_kernel() {
    const int gw   = (blockIdx.x * blockDim.x + threadIdx.x) >> 5;
    const int lane = threadIdx.x & 31;
    if (gw >= BN) return;
    const int half = lane >> 4;     // 0/1: which edge of the pair
    const int sub  = lane & 15;     // 16B chunk within the row

    float4 accL = make_float4(0.f, 0.f, 0.f, 0.f);
    float4 accH = make_float4(0.f, 0.f, 0.f, 0.f);
    float4 vsL  = make_float4(0.f, 0.f, 0.f, 0.f);
    float4 vsH  = make_float4(0.f, 0.f, 0.f, 0.f);
    const int2 Z = make_int2(0, 0);             // offset 0, w == 0.0f

    // ---- loop A: bb edges (x only) ----
    {
        int n = g_cntA[gw * CSTR]; if (n > CAPB) n = CAPB;
        const int2* ep = g_entA + (size_t)gw * CAPB;
        const char* xb = (const char*)g_x16 + (size_t)sub * 16;
        int2 E = (half < n) ? __ldcs(ep + half) : Z;
        for (int e = 0; e < n; e += 2) {
            const int i2 = e + 2 + half;
            const int2 Enx = (i2 < n) ? __ldcs(ep + i2) : Z;
            const uint4 hv = *(const uint4*)(xb + E.x);
            cvt8_fma(accL, accH, __int_as_float(E.y), hv);
            E = Enx;
        }
    }

    // ---- loop B: bm edges (x + vq, unconditional) ----
    {
        int n = g_cntB[gw * CSTR]; if (n > CAPB) n = CAPB;
        const int2* ep = g_entB + (size_t)gw * CAPB;
        const char* xcw = (const char*)g_x16 + (size_t)BN * 256 + (size_t)sub * 16;
        const char* qb  = (const char*)g_vqp + (size_t)sub * 32;
        int2 E = (half < n) ? __ldcs(ep + half) : Z;
        for (int e = 0; e < n; e += 2) {
            const int i2 = e + 2 + half;
            const int2 Enx = (i2 < n) ? __ldcs(ep + i2) : Z;
            const uint4 hv = *(const uint4*)(xcw + (E.x >> 1));
            const float4 q0 = *(const float4*)(qb + E.x);
            const float4 q1 = *(const float4*)(qb + E.x + 16);
            const float w = __int_as_float(E.y);
            cvt8_fma(accL, accH, w, hv);
            vsL.x = fmaf(w, q0.x, vsL.x); vsL.y = fmaf(w, q0.y, vsL.y);
            vsL.z = fmaf(w, q0.z, vsL.z); vsL.w = fmaf(w, q0.w, vsL.w);
            vsH.x = fmaf(w, q1.x, vsH.x); vsH.y = fmaf(w, q1.y, vsH.y);
            vsH.z = fmaf(w, q1.z, vsH.z); vsH.w = fmaf(w, q1.w, vsH.w);
            E = Enx;
        }
    }

    // merge odd-edge half into even lanes
    accL.x += __shfl_xor_sync(0xFFFFFFFF, accL.x, 16);
    accL.y += __shfl_xor_sync(0xFFFFFFFF, accL.y, 16);
    accL.z += __shfl_xor_sync(0xFFFFFFFF, accL.z, 16);
    accL.w += __shfl_xor_sync(0xFFFFFFFF, accL.w, 16);
    accH.x += __shfl_xor_sync(0xFFFFFFFF, accH.x, 16);
    accH.y += __shfl_xor_sync(0xFFFFFFFF, accH.y, 16);
    accH.z += __shfl_xor_sync(0xFFFFFFFF, accH.z, 16);
    accH.w += __shfl_xor_sync(0xFFFFFFFF, accH.w, 16);
    vsL.x += __shfl_xor_sync(0xFFFFFFFF, vsL.x, 16);
    vsL.y += __shfl_xor_sync(0xFFFFFFFF, vsL.y, 16);
    vsL.z += __shfl_xor_sync(0xFFFFFFFF, vsL.z, 16);
    vsL.w += __shfl_xor_sync(0xFFFFFFFF, vsL.w, 16);
    vsH.x += __shfl_xor_sync(0xFFFFFFFF, vsH.x, 16);
    vsH.y += __shfl_xor_sync(0xFFFFFFFF, vsH.y, 16);
    vsH.z += __shfl_xor_sync(0xFFFFFFFF, vsH.z, 16);
    vsH.w += __shfl_xor_sync(0xFFFFFFFF, vsH.w, 16);

    if (half == 0) {
        __half2 p0 = __floats2half2_rn(accL.x, accL.y);
        __half2 p1 = __floats2half2_rn(accL.z, accL.w);
        __half2 p2 = __floats2half2_rn(accH.x, accH.y);
        __half2 p3 = __floats2half2_rn(accH.z, accH.w);
        uint4 pk;
        pk.x = *(unsigned*)&p0; pk.y = *(unsigned*)&p1;
        pk.z = *(unsigned*)&p2; pk.w = *(unsigned*)&p3;
        ((uint4*)(g_xagg16 + (size_t)gw * CC))[sub] = pk;
        float4* vp = (float4*)(g_vsum + (size_t)gw * CC + sub * 8);
        vp[0] = vsL;
        vp[1] = vsH;
    }
}

// ---------------------------------------------------------------------------
// info_dot: g_info += sum_r dot(X_B[r], vsum[r])  — pure streaming dot (exact).
// ---------------------------------------------------------------------------
__global__ void info_dot_kernel(const float* __restrict__ X) {
    __shared__ float red[256];
    const int tid = threadIdx.x;
    const size_t total4 = (size_t)BN * CC / 4;
    float p = 0.0f;
    for (size_t i = blockIdx.x * 256 + tid; i < total4; i += (size_t)gridDim.x * 256) {
        const float4 h = __ldcs(((const float4*)X) + i);
        const float4 v = __ldcs(((const float4*)g_vsum) + i);
        p += h.x * v.x + h.y * v.y + h.z * v.z + h.w * v.w;
    }
    red[tid] = p;
    __syncthreads();
    for (int st = 128; st > 0; st >>= 1) {
        if (tid < st) red[tid] += red[tid + st];
        __syncthreads();
    }
    if (tid == 0 && red[0] != 0.0f) atomicAdd(&g_info, red[0]);
}

// ---------------------------------------------------------------------------
// finalize: out_scalar = (g_info + sum b_conv[col]*vq[b,m,e]) * wr
// ---------------------------------------------------------------------------
__global__ void finalize_kernel(const float* __restrict__ vq_grad,
                                const float* __restrict__ b_conv,
                                const float* __restrict__ wr_p,
                                float* __restrict__ out_scalar) {
    __shared__ float red[256];
    float s = 0.0f;
    for (int idx = threadIdx.x; idx < NBR * MM * DD; idx += 256) {
        const int b = idx >> 13;
        const int e = idx & 31;
        s += b_conv[b * DD + e] * vq_grad[idx];
    }
    red[threadIdx.x] = s;
    __syncthreads();
    for (int st = 128; st > 0; st >>= 1) {
        if (threadIdx.x < st) red[threadIdx.x] += red[threadIdx.x + st];
        __syncthreads();
    }
    if (threadIdx.x == 0) *out_scalar = (red[0] + g_info) * wr_p[0];
}

// ---------------------------------------------------------------------------
// y_kernel (WMMA): Y[r,c] = (xagg16 @ W'16)[r,c] + b'[c] + X_B[r,c]
// ---------------------------------------------------------------------------
__global__ void y_kernel(const float* __restrict__ X,
                         float* __restrict__ Y) {
    __shared__ __align__(16) char sraw[49152];
    __half* As = (__half*)sraw;                   // [64][128]
    __half* Bs = (__half*)(sraw + 16384);         // [128][128]
    float*  Ob = (float*)sraw;                    // [64][128] (after loop)

    const int row0 = blockIdx.x * YROWS;
    const int tid  = threadIdx.x;

    for (int i = tid; i < 1024; i += 256) {
        const int r = i >> 4, c16 = i & 15;
        const int row = row0 + r;
        uint4 v = make_uint4(0, 0, 0, 0);
        if (row < BN) v = ((const uint4*)(g_xagg16 + (size_t)row * CC))[c16];
        ((uint4*)As)[i] = v;
    }
    for (int i = tid; i < 2048; i += 256)
        ((uint4*)Bs)[i] = ((const uint4*)g_wp16)[i];
    __syncthreads();

    const int w  = tid >> 5;
    const int rt = w >> 1;          // 0..3
    const int ch = w & 1;           // 0/1

    wmma::fragment<wmma::accumulator, 16, 16, 16, float> accf[4];
    #pragma unroll
    for (int t = 0; t < 4; t++) wmma::fill_fragment(accf[t], 0.0f);

    #pragma unroll
    for (int k = 0; k < 8; k++) {
        wmma::fragment<wmma::matrix_a, 16, 16, 16, __half, wmma::row_major> af;
        wmma::load_matrix_sync(af, As + (rt * 16) * CC + k * 16, CC);
        #pragma unroll
        for (int t = 0; t < 4; t++) {
            wmma::fragment<wmma::matrix_b, 16, 16, 16, __half, wmma::row_major> bf;
            wmma::load_matrix_sync(bf, Bs + (k * 16) * CC + ch * 64 + t * 16, CC);
            wmma::mma_sync(accf[t], af, bf, accf[t]);
        }
    }
    __syncthreads();   // done with As/Bs

    #pragma unroll
    for (int t = 0; t < 4; t++)
        wmma::store_matrix_sync(Ob + (rt * 16) * CC + ch * 64 + t * 16,
                                accf[t], CC, wmma::mem_row_major);
    __syncthreads();

    for (int i = tid; i < YROWS * 32; i += 256) {
        const int r = i >> 5, c4 = i & 31;
        const int row = row0 + r;
        if (row >= BN) continue;
        const float4 ov = ((const float4*)Ob)[r * 32 + c4];
        const float4 bv = ((const float4*)g_bp)[c4];
        const float4 xv = ((const float4*)(X + (size_t)row * CC))[c4];
        ((float4*)(Y + (size_t)row * CC))[c4] =
            make_float4(ov.x + bv.x + xv.x, ov.y + bv.y + xv.y,
                        ov.z + bv.z + xv.z, ov.w + bv.w + xv.w);
    }
}

// ---------------------------------------------------------------------------
extern "C" void kernel_launch(void* const* d_in, const int* in_sizes, int n_in,
                              void* d_out, int out_size) {
    const float* X_B      = (const float*)d_in[0];
    const int*   esrc_bb  = (const int*)  d_in[1];
    const int*   edst_bb  = (const int*)  d_in[2];
    const float* ew_bb    = (const float*)d_in[3];
    const int*   esrc_bm  = (const int*)  d_in[4];
    const int*   edst_bm  = (const int*)  d_in[5];
    const float* ew_bm    = (const float*)d_in[6];
    const int*   c_idx    = (const int*)  d_in[7];
    const float* wr       = (const float*)d_in[8];
    const float* codebook = (const float*)d_in[9];
    const float* vq_grad  = (const float*)d_in[10];
    const float* W_conv   = (const float*)d_in[11];
    const float* b_conv   = (const float*)d_in[12];
    const float* W_fc     = (const float*)d_in[13];
    const float* b_fc     = (const float*)d_in[14];
    float* out = (float*)d_out;

    const int Ebb  = in_sizes[1];
    const int Ebm  = in_sizes[4];
    const int Etot = Ebb + Ebm;

    prep_x_kernel<<<(NODES * 64 + 255) / 256, 256>>>(X_B, codebook,        // 1
                                                     vq_grad, wr);
    prep_w_kernel<<<CC + 1 + MM, 128>>>(W_conv, W_fc, b_conv, b_fc);       // 2
    fill_dst_kernel<<<(Etot + 255) / 256, 256>>>(esrc_bb, edst_bb, ew_bb,  // 3
                                                 esrc_bm, edst_bm, ew_bm,
                                                 c_idx, Ebb, Etot);
    gather_kernel<<<(BN * 32 + 255) / 256, 256>>>();                       // 4 <- profiled
    info_dot_kernel<<<1184, 256>>>(X_B);                                   // 5
    finalize_kernel<<<1, 256>>>(vq_grad, b_conv, wr, out + (out_size - 1));// 6
    y_kernel<<<(BN + YROWS - 1) / YROWS, 256>>>(X_B, out);                 // 7
}

// round 17
// speedup vs baseline: 1.0433x; 1.0433x over previous
#include <cuda_runtime.h>
#include <cuda_fp16.h>
#include <mma.h>
#include <cstdint>

using namespace nvcuda;

#define BN     50000
#define NBR    4
#define DD     32
#define CC     128          // NBR*DD
#define MM     256
#define NODES  (BN + MM)    // 50256
#define CAPB   64           // per-type bucket capacity (mean ~20)
#define CSTR   8            // counter stride (ints) -> 32B, no LTS false sharing
#define YROWS  64           // rows per y block

// scratch (static device globals — no allocation)
__device__ __half g_x16[(size_t)NODES * CC];   // 12.9MB X_in fp16 (gather src)
__device__ __half g_xagg16[(size_t)BN * CC];   // aggregation result (y input)
__device__ __half g_wp16[CC * CC];             // W' = blockdiag(W_conv)@W_fc, fp16
__device__ float  g_bp[CC];                    // b'  = b_conv@W_fc + b_fc
__device__ int    g_cntA[BN * CSTR];           // bb counters (32B apart)
__device__ int    g_cntB[BN * CSTR];           // bm counters (32B apart)
__device__ __align__(16) int2 g_entA[(size_t)BN * CAPB];  // bb: (x_byte_off, w)
__device__ __align__(16) int2 g_entB[(size_t)BN * CAPB];  // bm: (vq_byte_off, w)
__device__ float  g_vq32r[MM * CC];            // vq_grad re-laid [m][b*32+e]
__device__ float  g_vqp[MM * CC];              // vq' = vq @ Wblk^T (128KB, L1-hot)
__device__ float  g_vsum[(size_t)BN * CC];     // per-row sum w*vq' (fp32)
__device__ float  g_info;

// ---------------------------------------------------------------------------
// prep_x: x16 rows + zero counters + relayout vq_grad.
// ---------------------------------------------------------------------------
__global__ void prep_x_kernel(const float* __restrict__ X,
                              const float* __restrict__ codebook,
                              const float* __restrict__ vq_grad,
                              const float* __restrict__ wr_p) {
    const int idx = blockIdx.x * blockDim.x + threadIdx.x;   // NODES*64 half2 units
    if (idx < NODES * 64) {
        const int row = idx >> 6;
        const int c2  = idx & 63;           // half2 column (0..63)
        float2 v;
        if (row < BN) {
            v = ((const float2*)X)[(size_t)row * 64 + c2];
        } else {
            const float wr = wr_p[0];
            const int b = c2 >> 4, sub = c2 & 15, m = row - BN;
            v = ((const float2*)codebook)[((size_t)b * MM + m) * 16 + sub];
            v.x *= wr; v.y *= wr;
        }
        ((__half2*)g_x16)[idx] = __floats2half2_rn(v.x, v.y);
    }
    if (idx < NBR * MM * DD) {
        const int b = idx >> 13;
        const int m = (idx >> 5) & (MM - 1);
        const int e = idx & 31;
        g_vq32r[m * CC + b * DD + e] = vq_grad[idx];
    }
    if (idx < BN) { g_cntA[idx * CSTR] = 0; g_cntB[idx * CSTR] = 0; }
    if (idx == 0) g_info = 0.0f;
}

// ---------------------------------------------------------------------------
// prep_w: block 0..127 -> W'[k][*]; block 128 -> b'; block 129.. -> vq'[m][*]
// ---------------------------------------------------------------------------
__global__ void prep_w_kernel(const float* __restrict__ W_conv,
                              const float* __restrict__ W_fc,
                              const float* __restrict__ b_conv,
                              const float* __restrict__ b_fc) {
    const int t = threadIdx.x;              // 0..127
    const int blk = blockIdx.x;
    if (blk < CC) {
        const int b = blk >> 5, d = blk & 31;
        const float* wrow = W_conv + (b * DD + d) * DD;   // [e]
        float s = 0.0f;
        #pragma unroll
        for (int e = 0; e < DD; e++)
            s = fmaf(wrow[e], W_fc[(b * DD + e) * CC + t], s);
        g_wp16[blk * CC + t] = __float2half_rn(s);
    } else if (blk == CC) {
        float s = b_fc[t];
        for (int k = 0; k < CC; k++)
            s = fmaf(b_conv[k], W_fc[k * CC + t], s);
        g_bp[t] = s;
    } else {
        const int m = blk - CC - 1;
        const int b = t >> 5, d = t & 31;
        const float* wrow = W_conv + (b * DD + d) * DD;   // [e]
        const float* vrow = g_vq32r + m * CC + b * DD;    // [e]
        float s = 0.0f;
        #pragma unroll
        for (int e = 0; e < DD; e++)
            s = fmaf(wrow[e], vrow[e], s);
        g_vqp[m * CC + t] = s;
    }
}

// ---------------------------------------------------------------------------
// fill: dual buckets. bb edges -> entA (x byte off = src*256);
//       bm edges -> entB (vq byte off = c_indices[src]*512).
// ---------------------------------------------------------------------------
__global__ void fill_dst_kernel(const int* __restrict__ sbb, const int* __restrict__ dbb,
                                const float* __restrict__ wbb,
                                const int* __restrict__ sbm, const int* __restrict__ dbm,
                                const float* __restrict__ wbm,
                                const int* __restrict__ cidx, int Ebb, int Etot) {
    const int i = blockIdx.x * blockDim.x + threadIdx.x;
    if (i >= Etot) return;
    if (i < Ebb) {
        const int r = dbb[i];
        const int off = sbb[i] << 8;            // *256 bytes (fp16 row)
        const float w = wbb[i];
        const int pos = atomicAdd(&g_cntA[r * CSTR], 1);
        if (pos < CAPB)
            g_entA[(size_t)r * CAPB + pos] = make_int2(off, __float_as_int(w));
    } else {
        const int j = i - Ebb;
        const int r = dbm[j];
        const int off = cidx[sbm[j]] << 9;      // m*512 bytes (fp32 vq' row)
        const float w = wbm[j];
        const int pos = atomicAdd(&g_cntB[r * CSTR], 1);
        if (pos < CAPB)
            g_entB[(size_t)r * CAPB + pos] = make_int2(off, __float_as_int(w));
    }
}

// ---------------------------------------------------------------------------
// gather v4 (4th launch -> profiled): round-15 structure (warp/row, 4-wide
// MLP) + self-padded buckets (no per-entry predication) + paired uint4
// entry loads (2 entries per LDG.128) + occupancy bound.
// ---------------------------------------------------------------------------
__device__ __forceinline__ void xfma(float4& acc, float w, uint2 hv) {
    const float2 f0 = __half22float2(*(const __half2*)&hv.x);
    const float2 f1 = __half22float2(*(const __half2*)&hv.y);
    acc.x = fmaf(w, f0.x, acc.x); acc.y = fmaf(w, f0.y, acc.y);
    acc.z = fmaf(w, f1.x, acc.z); acc.w = fmaf(w, f1.y, acc.w);
}

__global__ void __launch_bounds__(256, 6) gather_kernel() {
    const int gw   = (blockIdx.x * blockDim.x + threadIdx.x) >> 5;
    const int lane = threadIdx.x & 31;
    if (gw >= BN) return;

    int nA = g_cntA[gw * CSTR]; if (nA > CAPB) nA = CAPB;
    int nB = g_cntB[gw * CSTR]; if (nB > CAPB) nB = CAPB;
    const int padA = (nA + 3) & ~3;
    const int padB = (nB + 3) & ~3;
    int2* epA = g_entA + (size_t)gw * CAPB;
    int2* epB = g_entB + (size_t)gw * CAPB;
    // pad buckets to multiple of 4 with zero-weight entries (exact no-ops)
    if (lane < padA - nA) epA[nA + lane] = make_int2(0, 0);
    if (lane < padB - nB) epB[nB + lane] = make_int2(0, 0);
    __syncwarp();
    __threadfence_block();

    float4 acc = make_float4(0.f, 0.f, 0.f, 0.f);
    float4 vs  = make_float4(0.f, 0.f, 0.f, 0.f);
    const uint4 Z4 = make_uint4(0, 0, 0, 0);
    const char* xb = (const char*)g_x16 + (size_t)lane * 8;

    // ---- loop A: bb edges (x only) ----
    {
        const uint4* ep4 = (const uint4*)epA;   // 2 entries per uint4
        uint4 P0 = (0 < padA) ? __ldcs(ep4 + 0) : Z4;
        uint4 P1 = (2 < padA) ? __ldcs(ep4 + 1) : Z4;
        for (int e = 0; e < padA; e += 4) {
            const int q = e >> 1;
            const uint4 N0 = (e + 4 < padA) ? __ldcs(ep4 + q + 2) : Z4;
            const uint4 N1 = (e + 6 < padA) ? __ldcs(ep4 + q + 3) : Z4;
            const uint2 h0 = *(const uint2*)(xb + P0.x);
            const uint2 h1 = *(const uint2*)(xb + P0.z);
            const uint2 h2 = *(const uint2*)(xb + P1.x);
            const uint2 h3 = *(const uint2*)(xb + P1.z);
            xfma(acc, __int_as_float(P0.y), h0);
            xfma(acc, __int_as_float(P0.w), h1);
            xfma(acc, __int_as_float(P1.y), h2);
            xfma(acc, __int_as_float(P1.w), h3);
            P0 = N0; P1 = N1;
        }
    }

    // ---- loop B: bm edges (x + vq, unconditional) ----
    {
        const uint4* ep4 = (const uint4*)epB;
        const char* xcw = (const char*)g_x16 + (size_t)BN * 256 + (size_t)lane * 8;
        const char* qb  = (const char*)g_vqp + (size_t)lane * 16;
        uint4 P0 = (0 < padB) ? __ldcs(ep4 + 0) : Z4;
        uint4 P1 = (2 < padB) ? __ldcs(ep4 + 1) : Z4;
        for (int e = 0; e < padB; e += 4) {
            const int q = e >> 1;
            const uint4 N0 = (e + 4 < padB) ? __ldcs(ep4 + q + 2) : Z4;
            const uint4 N1 = (e + 6 < padB) ? __ldcs(ep4 + q + 3) : Z4;
            const uint2 h0 = *(const uint2*)(xcw + (P0.x >> 1));
            const uint2 h1 = *(const uint2*)(xcw + (P0.z >> 1));
            const uint2 h2 = *(const uint2*)(xcw + (P1.x >> 1));
            const uint2 h3 = *(const uint2*)(xcw + (P1.z >> 1));
            const float4 q0 = *(const float4*)(qb + P0.x);
            const float4 q1 = *(const float4*)(qb + P0.z);
            const float4 q2 = *(const float4*)(qb + P1.x);
            const float4 q3 = *(const float4*)(qb + P1.z);
            const float w0 = __int_as_float(P0.y);
            const float w1 = __int_as_float(P0.w);
            const float w2 = __int_as_float(P1.y);
            const float w3 = __int_as_float(P1.w);
            xfma(acc, w0, h0); xfma(acc, w1, h1);
            xfma(acc, w2, h2); xfma(acc, w3, h3);
            vs.x = fmaf(w0, q0.x, vs.x); vs.y = fmaf(w0, q0.y, vs.y);
            vs.z = fmaf(w0, q0.z, vs.z); vs.w = fmaf(w0, q0.w, vs.w);
            vs.x = fmaf(w1, q1.x, vs.x); vs.y = fmaf(w1, q1.y, vs.y);
            vs.z = fmaf(w1, q1.z, vs.z); vs.w = fmaf(w1, q1.w, vs.w);
            vs.x = fmaf(w2, q2.x, vs.x); vs.y = fmaf(w2, q2.y, vs.y);
            vs.z = fmaf(w2, q2.z, vs.z); vs.w = fmaf(w2, q2.w, vs.w);
            vs.x = fmaf(w3, q3.x, vs.x); vs.y = fmaf(w3, q3.y, vs.y);
            vs.z = fmaf(w3, q3.z, vs.z); vs.w = fmaf(w3, q3.w, vs.w);
            P0 = N0; P1 = N1;
        }
    }

    __half2 o0 = __floats2half2_rn(acc.x, acc.y);
    __half2 o1 = __floats2half2_rn(acc.z, acc.w);
    uint2 pk;
    pk.x = *(unsigned*)&o0;
    pk.y = *(unsigned*)&o1;
    ((uint2*)(g_xagg16 + (size_t)gw * CC))[lane] = pk;
    ((float4*)(g_vsum + (size_t)gw * CC))[lane] = vs;
}

// ---------------------------------------------------------------------------
// info_dot: g_info += sum_r dot(X_B[r], vsum[r])  — pure streaming dot (exact).
// ---------------------------------------------------------------------------
__global__ void info_dot_kernel(const float* __restrict__ X) {
    __shared__ float red[256];
    const int tid = threadIdx.x;
    const size_t total4 = (size_t)BN * CC / 4;
    float p = 0.0f;
    for (size_t i = blockIdx.x * 256 + tid; i < total4; i += (size_t)gridDim.x * 256) {
        const float4 h = __ldcs(((const float4*)X) + i);
        const float4 v = __ldcs(((const float4*)g_vsum) + i);
        p += h.x * v.x + h.y * v.y + h.z * v.z + h.w * v.w;
    }
    red[tid] = p;
    __syncthreads();
    for (int st = 128; st > 0; st >>= 1) {
        if (tid < st) red[tid] += red[tid + st];
        __syncthreads();
    }
    if (tid == 0 && red[0] != 0.0f) atomicAdd(&g_info, red[0]);
}

// ---------------------------------------------------------------------------
// finalize: out_scalar = (g_info + sum b_conv[col]*vq[b,m,e]) * wr
// ---------------------------------------------------------------------------
__global__ void finalize_kernel(const float* __restrict__ vq_grad,
                                const float* __restrict__ b_conv,
                                const float* __restrict__ wr_p,
                                float* __restrict__ out_scalar) {
    __shared__ float red[256];
    float s = 0.0f;
    for (int idx = threadIdx.x; idx < NBR * MM * DD; idx += 256) {
        const int b = idx >> 13;
        const int e = idx & 31;
        s += b_conv[b * DD + e] * vq_grad[idx];
    }
    red[threadIdx.x] = s;
    __syncthreads();
    for (int st = 128; st > 0; st >>= 1) {
        if (threadIdx.x < st) red[threadIdx.x] += red[threadIdx.x + st];
        __syncthreads();
    }
    if (threadIdx.x == 0) *out_scalar = (red[0] + g_info) * wr_p[0];
}

// ---------------------------------------------------------------------------
// y_kernel (WMMA): Y[r,c] = (xagg16 @ W'16)[r,c] + b'[c] + X_B[r,c]
// ---------------------------------------------------------------------------
__global__ void y_kernel(const float* __restrict__ X,
                         float* __restrict__ Y) {
    __shared__ __align__(16) char sraw[49152];
    __half* As = (__half*)sraw;                   // [64][128]
    __half* Bs = (__half*)(sraw + 16384);         // [128][128]
    float*  Ob = (float*)sraw;                    // [64][128] (after loop)

    const int row0 = blockIdx.x * YROWS;
    const int tid  = threadIdx.x;

    for (int i = tid; i < 1024; i += 256) {
        const int r = i >> 4, c16 = i & 15;
        const int row = row0 + r;
        uint4 v = make_uint4(0, 0, 0, 0);
        if (row < BN) v = ((const uint4*)(g_xagg16 + (size_t)row * CC))[c16];
        ((uint4*)As)[i] = v;
    }
    for (int i = tid; i < 2048; i += 256)
        ((uint4*)Bs)[i] = ((const uint4*)g_wp16)[i];
    __syncthreads();

    const int w  = tid >> 5;
    const int rt = w >> 1;          // 0..3
    const int ch = w & 1;           // 0/1

    wmma::fragment<wmma::accumulator, 16, 16, 16, float> accf[4];
    #pragma unroll
    for (int t = 0; t < 4; t++) wmma::fill_fragment(accf[t], 0.0f);

    #pragma unroll
    for (int k = 0; k < 8; k++) {
        wmma::fragment<wmma::matrix_a, 16, 16, 16, __half, wmma::row_major> af;
        wmma::load_matrix_sync(af, As + (rt * 16) * CC + k * 16, CC);
        #pragma unroll
        for (int t = 0; t < 4; t++) {
            wmma::fragment<wmma::matrix_b, 16, 16, 16, __half, wmma::row_major> bf;
            wmma::load_matrix_sync(bf, Bs + (k * 16) * CC + ch * 64 + t * 16, CC);
            wmma::mma_sync(accf[t], af, bf, accf[t]);
        }
    }
    __syncthreads();   // done with As/Bs

    #pragma unroll
    for (int t = 0; t < 4; t++)
        wmma::store_matrix_sync(Ob + (rt * 16) * CC + ch * 64 + t * 16,
                                accf[t], CC, wmma::mem_row_major);
    __syncthreads();

    for (int i = tid; i < YROWS * 32; i += 256) {
        const int r = i >> 5, c4 = i & 31;
        const int row = row0 + r;
        if (row >= BN) continue;
        const float4 ov = ((const float4*)Ob)[r * 32 + c4];
        const float4 bv = ((const float4*)g_bp)[c4];
        const float4 xv = ((const float4*)(X + (size_t)row * CC))[c4];
        ((float4*)(Y + (size_t)row * CC))[c4] =
            make_float4(ov.x + bv.x + xv.x, ov.y + bv.y + xv.y,
                        ov.z + bv.z + xv.z, ov.w + bv.w + xv.w);
    }
}

// ---------------------------------------------------------------------------
extern "C" void kernel_launch(void* const* d_in, const int* in_sizes, int n_in,
                              void* d_out, int out_size) {
    const float* X_B      = (const float*)d_in[0];
    const int*   esrc_bb  = (const int*)  d_in[1];
    const int*   edst_bb  = (const int*)  d_in[2];
    const float* ew_bb    = (const float*)d_in[3];
    const int*   esrc_bm  = (const int*)  d_in[4];
    const int*   edst_bm  = (const int*)  d_in[5];
    const float* ew_bm    = (const float*)d_in[6];
    const int*   c_idx    = (const int*)  d_in[7];
    const float* wr       = (const float*)d_in[8];
    const float* codebook = (const float*)d_in[9];
    const float* vq_grad  = (const float*)d_in[10];
    const float* W_conv   = (const float*)d_in[11];
    const float* b_conv   = (const float*)d_in[12];
    const float* W_fc     = (const float*)d_in[13];
    const float* b_fc     = (const float*)d_in[14];
    float* out = (float*)d_out;

    const int Ebb  = in_sizes[1];
    const int Ebm  = in_sizes[4];
    const int Etot = Ebb + Ebm;

    prep_x_kernel<<<(NODES * 64 + 255) / 256, 256>>>(X_B, codebook,        // 1
                                                     vq_grad, wr);
    prep_w_kernel<<<CC + 1 + MM, 128>>>(W_conv, W_fc, b_conv, b_fc);       // 2
    fill_dst_kernel<<<(Etot + 255) / 256, 256>>>(esrc_bb, edst_bb, ew_bb,  // 3
                                                 esrc_bm, edst_bm, ew_bm,
                                                 c_idx, Ebb, Etot);
    gather_kernel<<<(BN * 32 + 255) / 256, 256>>>();                       // 4 <- profiled
    info_dot_kernel<<<1184, 256>>>(X_B);                                   // 5
    finalize_kernel<<<1, 256>>>(vq_grad, b_conv, wr, out + (out_size - 1));// 6
    y_kernel<<<(BN + YROWS - 1) / YROWS, 256>>>(X_B, out);                 // 7
}